// round 2
// baseline (speedup 1.0000x reference)
#include <cuda_runtime.h>
#include <math_constants.h>
#include <cstdint>

#define KC 200      // clusters
#define DZ 64       // selective dim
#define SMAX 60000  // points (compile-time upper bound for scratch)

// ---------------- scratch (static device globals; no allocation) -------------
__device__ float g_L[(size_t)SMAX * KC];    // logits, K-major: [k*s + i]
__device__ float g_Qc[(size_t)SMAX * KC];   // clipped Q, point-major: [i*KC + k]
__device__ float g_znorm[SMAX];
__device__ int   g_is64;

// ---------------- K0: probe whether D is int32 or int64 ---------------------
__global__ void k0_detect(const void* __restrict__ Dv) {
    if (threadIdx.x == 0 && blockIdx.x == 0) {
        const long long* p = (const long long*)Dv;
        int is64 = 1;
        // If the data is int32, reading as int64 packs two random ints; the
        // high word is almost surely nonzero somewhere in the first 32 words.
        for (int t = 0; t < 32; ++t) {
            long long v = p[t];
            if (v < 0 || v > 0x7FFFFFFFLL) { is64 = 0; break; }
        }
        g_is64 = is64;
    }
}

// ---------------- K1: logits L[k,i] = x_i . mu_k - 0.5*||mu_k||^2 -----------
__global__ void __launch_bounds__(256, 2) k1_logits(
    const float* __restrict__ Z, const float* __restrict__ S,
    const float* __restrict__ sel_mu, const float* __restrict__ spa_mu,
    int s)
{
    extern __shared__ float smem[];
    float* mu_s  = smem;                 // [KC][DZ]
    float* spa_s = smem + KC * DZ;       // [KC][4] (padded)
    float* mn_s  = spa_s + KC * 4;       // [KC]  ||mu||^2 (sel+spa)

    const int t = threadIdx.x;
    for (int idx = t; idx < KC * DZ; idx += 256) mu_s[idx] = sel_mu[idx];
    for (int k = t; k < KC; k += 256) {
        spa_s[k * 4 + 0] = spa_mu[k * 3 + 0];
        spa_s[k * 4 + 1] = spa_mu[k * 3 + 1];
        spa_s[k * 4 + 2] = spa_mu[k * 3 + 2];
        spa_s[k * 4 + 3] = 0.f;
    }
    __syncthreads();
    for (int k = t; k < KC; k += 256) {
        const float4* m4 = (const float4*)(mu_s + k * DZ);
        float a = 0.f;
        #pragma unroll
        for (int j = 0; j < DZ / 4; ++j) {
            float4 m = m4[j];
            a += m.x * m.x + m.y * m.y + m.z * m.z + m.w * m.w;
        }
        float4 sp = *(const float4*)(spa_s + k * 4);
        a += sp.x * sp.x + sp.y * sp.y + sp.z * sp.z;
        mn_s[k] = a;
    }
    __syncthreads();

    const int i = blockIdx.x * 256 + t;
    if (i >= s) return;

    // x row into registers
    float4 z4[DZ / 4];
    const float4* Zp = (const float4*)(Z + (size_t)i * DZ);
    #pragma unroll
    for (int j = 0; j < DZ / 4; ++j) z4[j] = Zp[j];
    const float s0 = S[(size_t)i * 3 + 0];
    const float s1 = S[(size_t)i * 3 + 1];
    const float s2 = S[(size_t)i * 3 + 2];

    float zn = s0 * s0 + s1 * s1 + s2 * s2;
    #pragma unroll
    for (int j = 0; j < DZ / 4; ++j)
        zn += z4[j].x * z4[j].x + z4[j].y * z4[j].y +
              z4[j].z * z4[j].z + z4[j].w * z4[j].w;
    g_znorm[i] = zn;

    #pragma unroll 2
    for (int k = 0; k < KC; ++k) {
        const float4* m4 = (const float4*)(mu_s + k * DZ);
        float a0 = 0.f, a1 = 0.f, a2 = 0.f, a3 = 0.f;
        #pragma unroll
        for (int j = 0; j < DZ / 4; ++j) {
            float4 m = m4[j];                  // LDS.128 broadcast
            a0 += z4[j].x * m.x;
            a1 += z4[j].y * m.y;
            a2 += z4[j].z * m.z;
            a3 += z4[j].w * m.w;
        }
        float4 sp = *(const float4*)(spa_s + k * 4);
        float dot = (a0 + a1) + (a2 + a3)
                  + s0 * sp.x + s1 * sp.y + s2 * sp.z;
        g_L[(size_t)k * s + i] = dot - 0.5f * mn_s[k];   // coalesced store
    }
}

// ---------------- K1b: softmax per point, point energy, store clipped Q -----
#define P1B 32
__global__ void __launch_bounds__(256) k1b_softmax(float* __restrict__ out,
                                                   int s, float cpoint)
{
    __shared__ float tile[KC][P1B + 1];          // 200*33*4 = 26.4KB
    const int t = threadIdx.x;
    const int lane = t & 31, w = t >> 5;
    const int i0 = blockIdx.x * P1B;

    // load L tile, K-major reads are coalesced
    #pragma unroll
    for (int j = 0; j < KC / 8; ++j) {           // 8 warps x 25 rows
        int k = w * (KC / 8) + j;
        int i = i0 + lane;
        tile[k][lane] = (i < s) ? g_L[(size_t)k * s + i] : -1e30f;
    }
    __syncthreads();

    const int p = t >> 3, sub = t & 7;           // 8 threads per point
    float mx = -CUDART_INF_F;
    #pragma unroll
    for (int m = 0; m < KC / 8; ++m)
        mx = fmaxf(mx, tile[sub + 8 * m][p]);
    #pragma unroll
    for (int o = 4; o; o >>= 1)
        mx = fmaxf(mx, __shfl_xor_sync(0xffffffffu, mx, o, 8));

    float se = 0.f, sl = 0.f;
    #pragma unroll
    for (int m = 0; m < KC / 8; ++m) {
        int k = sub + 8 * m;
        float L = tile[k][p];
        float e = __expf(L - mx);
        se += e;
        sl += e * L;
        tile[k][p] = e;                          // overwrite with exp
    }
    #pragma unroll
    for (int o = 4; o; o >>= 1) {
        se += __shfl_xor_sync(0xffffffffu, se, o, 8);
        sl += __shfl_xor_sync(0xffffffffu, sl, o, 8);
    }
    const float inv = 1.0f / se;

    const int i = i0 + p;
    if (i < s) {
        if (sub == 0)
            out[i] = -(sl * inv) + 0.5f * g_znorm[i] + cpoint;
        #pragma unroll
        for (int m = 0; m < KC / 8; ++m) {
            int k = sub + 8 * m;
            float q = tile[k][p] * inv;
            q = fminf(fmaxf(q, 1e-6f), 1.0f - 1e-6f);
            g_Qc[(size_t)i * KC + k] = q;
        }
    }
}

// ---------------- K2: doublet energy via neighbor-row dot products ----------
__global__ void __launch_bounds__(256) k2_doublet(float* __restrict__ out,
                                                  const void* __restrict__ Dv,
                                                  int s, int n)
{
    const int t = threadIdx.x;
    const int lane = t & 31, w = t >> 5;
    const int i = blockIdx.x * 8 + w;
    if (i >= s) return;

    float own[7];
    #pragma unroll
    for (int j = 0; j < 7; ++j) {
        int k = 32 * j + lane;
        own[j] = (k < KC) ? g_Qc[(size_t)i * KC + k] : 0.f;
    }

    const bool is64 = (g_is64 != 0);
    float doublet = 0.f;
    for (int nb = 0; nb < n; ++nb) {
        long long d = is64
            ? ((const long long*)Dv)[(size_t)i * n + nb]
            : (long long)((const int*)Dv)[(size_t)i * n + nb];
        if (d >= 0 && d < s) {
            const float* __restrict__ row = g_Qc + (size_t)d * KC;
            float acc = 0.f;
            #pragma unroll
            for (int j = 0; j < 7; ++j) {
                int k = 32 * j + lane;
                if (k < KC) acc += own[j] * row[k];
            }
            #pragma unroll
            for (int o = 16; o; o >>= 1)
                acc += __shfl_xor_sync(0xffffffffu, acc, o);
            doublet -= __logf(acc);
        }
    }
    if (lane == 0) out[i] += doublet;
}

// ---------------- launch -----------------------------------------------------
extern "C" void kernel_launch(void* const* d_in, const int* in_sizes, int n_in,
                              void* d_out, int out_size)
{
    const float* Z      = (const float*)d_in[0];
    const float* S      = (const float*)d_in[1];
    const void*  D      = d_in[2];
    const float* sel_mu = (const float*)d_in[3];
    const float* spa_mu = (const float*)d_in[4];
    float* out = (float*)d_out;

    const int s  = in_sizes[1] / 3;   // 60000
    const int dz = in_sizes[0] / s;   // 64
    const int n  = in_sizes[2] / s;   // 6
    const float cpoint = 0.5f * (float)(dz + 3) * 1.8378770664093453f;

    const size_t smem1 = (size_t)(KC * DZ + KC * 4 + KC) * sizeof(float); // 55.2KB
    static bool attr_set = false;
    if (!attr_set) {
        cudaFuncSetAttribute(k1_logits,
                             cudaFuncAttributeMaxDynamicSharedMemorySize,
                             (int)smem1);
        attr_set = true;
    }

    k0_detect<<<1, 32>>>(D);
    k1_logits<<<(s + 255) / 256, 256, smem1>>>(Z, S, sel_mu, spa_mu, s);
    k1b_softmax<<<(s + P1B - 1) / P1B, 256>>>(out, s, cpoint);
    k2_doublet<<<(s + 7) / 8, 256>>>(out, D, s, n);
}

// round 4
// speedup vs baseline: 1.4463x; 1.4463x over previous
#include <cuda_runtime.h>
#include <cuda_bf16.h>
#include <math_constants.h>
#include <cstdint>

#define KC     200
#define NT     26            // n-tiles of 8 -> KPAD = 208
#define NTS    25            // tiles actually stored (200 cols)
#define KPAD   (NT * 8)
#define DZ     64
#define TILE_M 128
#define SMAX   60000
#define APITCH 72            // bf16 elements per smem row (144B, conflict-free)

// ---------------- scratch ----------------------------------------------------
__device__ __align__(16) __nv_bfloat16 g_Qc[(size_t)SMAX * KC];  // 24MB
__device__ int g_is64;

// ---------------- helpers ----------------------------------------------------
__device__ __forceinline__ uint32_t pack_bf2(float a, float b) {
    __nv_bfloat162 t = __floats2bfloat162_rn(a, b);
    return *(uint32_t*)&t;
}

__device__ __forceinline__ void mma_bf16(float c[4], const uint32_t a[4],
                                         uint32_t b0, uint32_t b1) {
    asm volatile(
        "mma.sync.aligned.m16n8k16.row.col.f32.bf16.bf16.f32 "
        "{%0,%1,%2,%3}, {%4,%5,%6,%7}, {%8,%9}, {%0,%1,%2,%3};"
        : "+f"(c[0]), "+f"(c[1]), "+f"(c[2]), "+f"(c[3])
        : "r"(a[0]), "r"(a[1]), "r"(a[2]), "r"(a[3]), "r"(b0), "r"(b1));
}

// ---------------- K0: probe int32 vs int64 D ---------------------------------
__global__ void k0_detect(const void* __restrict__ Dv) {
    if (threadIdx.x == 0 && blockIdx.x == 0) {
        const long long* p = (const long long*)Dv;
        int is64 = 1;
        for (int t = 0; t < 32; ++t) {
            long long v = p[t];
            if (v < 0 || v > 0x7FFFFFFFLL) { is64 = 0; break; }
        }
        g_is64 = is64;
    }
}

// ---------------- K1: fused logits (HMMA) + softmax + point + Qc -------------
// smem layout (bytes):
//   cf  : float4[KPAD]   (p0,p1,p2, 0.5*||mu||^2)          3328
//   rc  : float4[TILE_M] (s0,s1,s2, ||x||^2)               2048
//   Ah/Al : bf16 [TILE_M][APITCH] each                    18432 * 2
//   Bh/Bl : bf16 [KPAD][APITCH]  each                     29952 * 2
#define OFF_RC  (KPAD * 16)
#define OFF_AH  (OFF_RC + TILE_M * 16)
#define OFF_AL  (OFF_AH + TILE_M * APITCH * 2)
#define OFF_BH  (OFF_AL + TILE_M * APITCH * 2)
#define OFF_BL  (OFF_BH + KPAD * APITCH * 2)
#define SMEM_SZ (OFF_BL + KPAD * APITCH * 2)   // 102144 B

__global__ void __launch_bounds__(256, 1) k1_fused(
    const float* __restrict__ Z, const float* __restrict__ S,
    const float* __restrict__ sel_mu, const float* __restrict__ spa_mu,
    float* __restrict__ out, int s, float cpoint)
{
    extern __shared__ __align__(16) char smem[];
    float4* cfp = (float4*)smem;
    float4* rcp = (float4*)(smem + OFF_RC);
    __nv_bfloat16* Ah = (__nv_bfloat16*)(smem + OFF_AH);
    __nv_bfloat16* Al = (__nv_bfloat16*)(smem + OFF_AL);
    __nv_bfloat16* Bh = (__nv_bfloat16*)(smem + OFF_BH);
    __nv_bfloat16* Bl = (__nv_bfloat16*)(smem + OFF_BL);

    const int tid = threadIdx.x, lane = tid & 31, w = tid >> 5;
    const int g = lane >> 2, tg = lane & 3;
    const int i0 = blockIdx.x * TILE_M;

    // ---- stage A (Z tile) as bf16 hi/lo ----
    #pragma unroll 1
    for (int idx = tid; idx < TILE_M * 16; idx += 256) {
        const int row = idx >> 4, j4 = idx & 15;
        const int gi = i0 + row;
        float4 v = make_float4(0.f, 0.f, 0.f, 0.f);
        if (gi < s) v = ((const float4*)Z)[(size_t)gi * 16 + j4];
        const float hx = __bfloat162float(__float2bfloat16(v.x));
        const float hy = __bfloat162float(__float2bfloat16(v.y));
        const float hz = __bfloat162float(__float2bfloat16(v.z));
        const float hw = __bfloat162float(__float2bfloat16(v.w));
        uint32_t* dh = (uint32_t*)(Ah + row * APITCH + j4 * 4);
        dh[0] = pack_bf2(hx, hy); dh[1] = pack_bf2(hz, hw);
        uint32_t* dl = (uint32_t*)(Al + row * APITCH + j4 * 4);
        dl[0] = pack_bf2(v.x - hx, v.y - hy);
        dl[1] = pack_bf2(v.z - hz, v.w - hw);
    }

    // ---- stage B (sel_mu) as bf16 hi/lo ----
    #pragma unroll 1
    for (int idx = tid; idx < KPAD * 16; idx += 256) {
        const int row = idx >> 4, j4 = idx & 15;
        float4 v = make_float4(0.f, 0.f, 0.f, 0.f);
        if (row < KC) v = ((const float4*)sel_mu)[row * 16 + j4];
        const float hx = __bfloat162float(__float2bfloat16(v.x));
        const float hy = __bfloat162float(__float2bfloat16(v.y));
        const float hz = __bfloat162float(__float2bfloat16(v.z));
        const float hw = __bfloat162float(__float2bfloat16(v.w));
        uint32_t* dh = (uint32_t*)(Bh + row * APITCH + j4 * 4);
        dh[0] = pack_bf2(hx, hy); dh[1] = pack_bf2(hz, hw);
        uint32_t* dl = (uint32_t*)(Bl + row * APITCH + j4 * 4);
        dl[0] = pack_bf2(v.x - hx, v.y - hy);
        dl[1] = pack_bf2(v.z - hz, v.w - hw);
    }

    // ---- per-cluster coefficients ----
    #pragma unroll 1
    for (int k = tid; k < KPAD; k += 256) {
        float4 cf = make_float4(0.f, 0.f, 0.f, 1e30f);
        if (k < KC) {
            const float a = spa_mu[3 * k], b = spa_mu[3 * k + 1], c = spa_mu[3 * k + 2];
            float mn = a * a + b * b + c * c;
            const float4* mr = (const float4*)sel_mu + (size_t)k * 16;
            #pragma unroll
            for (int j = 0; j < 16; ++j) {
                float4 m = mr[j];
                mn += m.x * m.x + m.y * m.y + m.z * m.z + m.w * m.w;
            }
            cf = make_float4(a, b, c, 0.5f * mn);
        }
        cfp[k] = cf;
    }

    // ---- per-row constants ----
    if (tid < TILE_M) {
        const int gi = i0 + tid;
        float4 rc = make_float4(0.f, 0.f, 0.f, 0.f);
        if (gi < s) {
            float zn = 0.f;
            const float4* zr = (const float4*)Z + (size_t)gi * 16;
            #pragma unroll
            for (int j = 0; j < 16; ++j) {
                float4 z = zr[j];
                zn += z.x * z.x + z.y * z.y + z.z * z.z + z.w * z.w;
            }
            rc.x = S[(size_t)3 * gi];
            rc.y = S[(size_t)3 * gi + 1];
            rc.z = S[(size_t)3 * gi + 2];
            rc.w = zn + rc.x * rc.x + rc.y * rc.y + rc.z * rc.z;
        }
        rcp[tid] = rc;
    }
    __syncthreads();

    // ---- MMA mainloop: acc[t] += Ah*Bh + Ah*Bl + Al*Bh ----
    float acc[NT][4];
    #pragma unroll
    for (int t = 0; t < NT; ++t)
        acc[t][0] = acc[t][1] = acc[t][2] = acc[t][3] = 0.f;

    const int r0 = w * 16 + g;
    #pragma unroll
    for (int ks = 0; ks < 4; ++ks) {
        const int kb = ks * 16 + 2 * tg;
        uint32_t a_h[4], a_l[4];
        a_h[0] = *(const uint32_t*)(Ah + r0 * APITCH + kb);
        a_h[1] = *(const uint32_t*)(Ah + (r0 + 8) * APITCH + kb);
        a_h[2] = *(const uint32_t*)(Ah + r0 * APITCH + kb + 8);
        a_h[3] = *(const uint32_t*)(Ah + (r0 + 8) * APITCH + kb + 8);
        a_l[0] = *(const uint32_t*)(Al + r0 * APITCH + kb);
        a_l[1] = *(const uint32_t*)(Al + (r0 + 8) * APITCH + kb);
        a_l[2] = *(const uint32_t*)(Al + r0 * APITCH + kb + 8);
        a_l[3] = *(const uint32_t*)(Al + (r0 + 8) * APITCH + kb + 8);
        #pragma unroll
        for (int t = 0; t < NT; ++t) {
            const __nv_bfloat16* bh = Bh + (t * 8 + g) * APITCH + kb;
            const __nv_bfloat16* bl = Bl + (t * 8 + g) * APITCH + kb;
            const uint32_t bh0 = *(const uint32_t*)bh;
            const uint32_t bh1 = *(const uint32_t*)(bh + 8);
            const uint32_t bl0 = *(const uint32_t*)bl;
            const uint32_t bl1 = *(const uint32_t*)(bl + 8);
            mma_bf16(acc[t], a_h, bh0, bh1);
            mma_bf16(acc[t], a_h, bl0, bl1);
            mma_bf16(acc[t], a_l, bh0, bh1);
        }
    }

    // ---- epilogue: logits -> softmax (rows r0, r0+8 per lane group) ----
    const float4 rc0 = rcp[r0];
    const float4 rc1 = rcp[r0 + 8];

    float m0 = -CUDART_INF_F, m1 = -CUDART_INF_F;
    #pragma unroll
    for (int t = 0; t < NT; ++t) {
        const float4 c0 = cfp[8 * t + 2 * tg];
        const float4 c1 = cfp[8 * t + 2 * tg + 1];
        acc[t][0] += rc0.x * c0.x + rc0.y * c0.y + rc0.z * c0.z - c0.w;
        acc[t][1] += rc0.x * c1.x + rc0.y * c1.y + rc0.z * c1.z - c1.w;
        acc[t][2] += rc1.x * c0.x + rc1.y * c0.y + rc1.z * c0.z - c0.w;
        acc[t][3] += rc1.x * c1.x + rc1.y * c1.y + rc1.z * c1.z - c1.w;
        m0 = fmaxf(m0, fmaxf(acc[t][0], acc[t][1]));
        m1 = fmaxf(m1, fmaxf(acc[t][2], acc[t][3]));
    }
    m0 = fmaxf(m0, __shfl_xor_sync(0xffffffffu, m0, 1));
    m0 = fmaxf(m0, __shfl_xor_sync(0xffffffffu, m0, 2));
    m1 = fmaxf(m1, __shfl_xor_sync(0xffffffffu, m1, 1));
    m1 = fmaxf(m1, __shfl_xor_sync(0xffffffffu, m1, 2));

    float se0 = 0.f, sl0 = 0.f, se1 = 0.f, sl1 = 0.f;
    #pragma unroll
    for (int t = 0; t < NT; ++t) {
        float e;
        e = __expf(acc[t][0] - m0); se0 += e; sl0 += e * acc[t][0]; acc[t][0] = e;
        e = __expf(acc[t][1] - m0); se0 += e; sl0 += e * acc[t][1]; acc[t][1] = e;
        e = __expf(acc[t][2] - m1); se1 += e; sl1 += e * acc[t][2]; acc[t][2] = e;
        e = __expf(acc[t][3] - m1); se1 += e; sl1 += e * acc[t][3]; acc[t][3] = e;
    }
    se0 += __shfl_xor_sync(0xffffffffu, se0, 1);
    se0 += __shfl_xor_sync(0xffffffffu, se0, 2);
    sl0 += __shfl_xor_sync(0xffffffffu, sl0, 1);
    sl0 += __shfl_xor_sync(0xffffffffu, sl0, 2);
    se1 += __shfl_xor_sync(0xffffffffu, se1, 1);
    se1 += __shfl_xor_sync(0xffffffffu, se1, 2);
    sl1 += __shfl_xor_sync(0xffffffffu, sl1, 1);
    sl1 += __shfl_xor_sync(0xffffffffu, sl1, 2);

    const float inv0 = 1.0f / se0, inv1 = 1.0f / se1;
    const int gr0 = i0 + r0, gr1 = gr0 + 8;
    if (tg == 0) {
        if (gr0 < s) out[gr0] = 0.5f * rc0.w + cpoint - sl0 * inv0;
        if (gr1 < s) out[gr1] = 0.5f * rc1.w + cpoint - sl1 * inv1;
    }

    // ---- store clipped Q as bf16 (point-major) ----
    uint32_t* q0p = (uint32_t*)(g_Qc + (size_t)gr0 * KC);
    uint32_t* q1p = (uint32_t*)(g_Qc + (size_t)gr1 * KC);
    const bool v0 = (gr0 < s), v1 = (gr1 < s);
    #pragma unroll
    for (int t = 0; t < NTS; ++t) {
        float qa = fminf(fmaxf(acc[t][0] * inv0, 1e-6f), 1.0f - 1e-6f);
        float qb = fminf(fmaxf(acc[t][1] * inv0, 1e-6f), 1.0f - 1e-6f);
        float qc = fminf(fmaxf(acc[t][2] * inv1, 1e-6f), 1.0f - 1e-6f);
        float qd = fminf(fmaxf(acc[t][3] * inv1, 1e-6f), 1.0f - 1e-6f);
        if (v0) q0p[4 * t + tg] = pack_bf2(qa, qb);
        if (v1) q1p[4 * t + tg] = pack_bf2(qc, qd);
    }
}

// ---------------- K2: doublet energy (warp/point, bf16 rows) -----------------
__global__ void __launch_bounds__(256) k2_doublet(float* __restrict__ out,
                                                  const void* __restrict__ Dv,
                                                  int s, int n)
{
    const int t = threadIdx.x, lane = t & 31, w = t >> 5;
    const int i = blockIdx.x * 8 + w;
    if (i >= s) return;

    const uint4* Q4 = (const uint4*)g_Qc;   // row = 25 uint4 (200 bf16)
    const uint4 zero4 = make_uint4(0, 0, 0, 0);
    const uint4 ov = (lane < NTS) ? Q4[(size_t)i * NTS + lane] : zero4;
    float of[8];
    {
        const uint32_t* p = (const uint32_t*)&ov;
        #pragma unroll
        for (int j = 0; j < 4; ++j) {
            float2 f = __bfloat1622float2(*(const __nv_bfloat162*)&p[j]);
            of[2 * j] = f.x; of[2 * j + 1] = f.y;
        }
    }
    const bool is64 = (g_is64 != 0);

    float doublet = 0.f;
    for (int base = 0; base < n; base += 6) {
        float acc[6]; int val[6];
        #pragma unroll
        for (int nb = 0; nb < 6; ++nb) {
            acc[nb] = 1.f; val[nb] = 0;
            const int q = base + nb;
            if (q < n) {
                long long d = is64 ? ((const long long*)Dv)[(size_t)i * n + q]
                                   : (long long)((const int*)Dv)[(size_t)i * n + q];
                val[nb] = (d >= 0 && d < s) ? 1 : 0;
                const size_t ridx = (size_t)(val[nb] ? (int)d : i) * NTS;
                const uint4 nv = (lane < NTS) ? Q4[ridx + lane] : zero4;
                const uint32_t* p = (const uint32_t*)&nv;
                float a = 0.f;
                #pragma unroll
                for (int j = 0; j < 4; ++j) {
                    float2 f = __bfloat1622float2(*(const __nv_bfloat162*)&p[j]);
                    a += of[2 * j] * f.x + of[2 * j + 1] * f.y;
                }
                acc[nb] = a;
            }
        }
        #pragma unroll
        for (int off = 16; off; off >>= 1) {
            #pragma unroll
            for (int nb = 0; nb < 6; ++nb)
                acc[nb] += __shfl_xor_sync(0xffffffffu, acc[nb], off);
        }
        #pragma unroll
        for (int nb = 0; nb < 6; ++nb)
            if (val[nb]) doublet -= __logf(acc[nb]);
    }
    if (lane == 0) out[i] += doublet;
}

// ---------------- launch -----------------------------------------------------
extern "C" void kernel_launch(void* const* d_in, const int* in_sizes, int n_in,
                              void* d_out, int out_size)
{
    const float* Z      = (const float*)d_in[0];
    const float* S      = (const float*)d_in[1];
    const void*  D      = d_in[2];
    const float* sel_mu = (const float*)d_in[3];
    const float* spa_mu = (const float*)d_in[4];
    float* out = (float*)d_out;

    const int s  = in_sizes[1] / 3;
    const int dz = in_sizes[0] / s;
    const int n  = in_sizes[2] / s;
    const float cpoint = 0.5f * (float)(dz + 3) * 1.8378770664093453f;

    static bool attr_set = false;
    if (!attr_set) {
        cudaFuncSetAttribute(k1_fused,
                             cudaFuncAttributeMaxDynamicSharedMemorySize,
                             SMEM_SZ);
        attr_set = true;
    }

    k0_detect<<<1, 32>>>(D);
    k1_fused<<<(s + TILE_M - 1) / TILE_M, 256, SMEM_SZ>>>(
        Z, S, sel_mu, spa_mu, out, s, cpoint);
    k2_doublet<<<(s + 7) / 8, 256>>>(out, D, s, n);
}

// round 5
// speedup vs baseline: 1.5250x; 1.0544x over previous
#include <cuda_runtime.h>
#include <cuda_bf16.h>
#include <math_constants.h>
#include <cstdint>

#define KC     200
#define NT     26            // total n-tiles of 8 -> KPAD = 208
#define NTW    13            // n-tiles per warp (pair-split)
#define KPAD   (NT * 8)
#define DZ     64
#define TILE_M 64
#define SMAX   60000
#define APITCH 72            // bf16 elems per smem row (144B, conflict-free)

// ---------------- scratch ----------------------------------------------------
__device__ __align__(16) __nv_bfloat16 g_Qc[(size_t)SMAX * KC + 8];

// ---------------- helpers ----------------------------------------------------
__device__ __forceinline__ uint32_t pack_bf2(float a, float b) {
    __nv_bfloat162 t = __floats2bfloat162_rn(a, b);
    return *(uint32_t*)&t;
}

__device__ __forceinline__ void mma_bf16(float c[4], const uint32_t a[4],
                                         uint32_t b0, uint32_t b1) {
    asm volatile(
        "mma.sync.aligned.m16n8k16.row.col.f32.bf16.bf16.f32 "
        "{%0,%1,%2,%3}, {%4,%5,%6,%7}, {%8,%9}, {%0,%1,%2,%3};"
        : "+f"(c[0]), "+f"(c[1]), "+f"(c[2]), "+f"(c[3])
        : "r"(a[0]), "r"(a[1]), "r"(a[2]), "r"(a[3]), "r"(b0), "r"(b1));
}

// ---------------- K1: fused logits (HMMA) + softmax + point + Qc -------------
// smem layout (bytes)
#define OFF_CF  0                              // float4[KPAD]        3328
#define OFF_RC  (OFF_CF + KPAD * 16)           // float4[TILE_M]      1024
#define OFF_ST  (OFF_RC + TILE_M * 16)         // float[3][64][2]     1536
#define OFF_AH  (OFF_ST + 1536)
#define OFF_AL  (OFF_AH + TILE_M * APITCH * 2)
#define OFF_BH  (OFF_AL + TILE_M * APITCH * 2)
#define OFF_BL  (OFF_BH + KPAD * APITCH * 2)
#define SMEM_SZ (OFF_BL + KPAD * APITCH * 2)   // 84224 B

__global__ void __launch_bounds__(256, 2) k1_fused(
    const float* __restrict__ Z, const float* __restrict__ S,
    const float* __restrict__ sel_mu, const float* __restrict__ spa_mu,
    float* __restrict__ out, int s, float cpoint)
{
    extern __shared__ __align__(16) char smem[];
    float4* cfp = (float4*)(smem + OFF_CF);
    float4* rcp = (float4*)(smem + OFF_RC);
    float*  stM  = (float*)(smem + OFF_ST);          // [64][2]
    float*  stSE = stM + 128;
    float*  stSL = stSE + 128;
    __nv_bfloat16* Ah = (__nv_bfloat16*)(smem + OFF_AH);
    __nv_bfloat16* Al = (__nv_bfloat16*)(smem + OFF_AL);
    __nv_bfloat16* Bh = (__nv_bfloat16*)(smem + OFF_BH);
    __nv_bfloat16* Bl = (__nv_bfloat16*)(smem + OFF_BL);

    const int tid = threadIdx.x, lane = tid & 31, w = tid >> 5;
    const int g = lane >> 2, tg = lane & 3;
    const int stripe = w >> 1, half = w & 1;
    const int i0 = blockIdx.x * TILE_M;

    // ---- stage A (Z tile) as bf16 hi/lo ----
    #pragma unroll 1
    for (int idx = tid; idx < TILE_M * 16; idx += 256) {
        const int row = idx >> 4, j4 = idx & 15;
        const int gi = i0 + row;
        float4 v = make_float4(0.f, 0.f, 0.f, 0.f);
        if (gi < s) v = ((const float4*)Z)[(size_t)gi * 16 + j4];
        const float hx = __bfloat162float(__float2bfloat16(v.x));
        const float hy = __bfloat162float(__float2bfloat16(v.y));
        const float hz = __bfloat162float(__float2bfloat16(v.z));
        const float hw = __bfloat162float(__float2bfloat16(v.w));
        uint32_t* dh = (uint32_t*)(Ah + row * APITCH + j4 * 4);
        dh[0] = pack_bf2(hx, hy); dh[1] = pack_bf2(hz, hw);
        uint32_t* dl = (uint32_t*)(Al + row * APITCH + j4 * 4);
        dl[0] = pack_bf2(v.x - hx, v.y - hy);
        dl[1] = pack_bf2(v.z - hz, v.w - hw);
    }

    // ---- stage B (sel_mu) as bf16 hi/lo ----
    #pragma unroll 1
    for (int idx = tid; idx < KPAD * 16; idx += 256) {
        const int row = idx >> 4, j4 = idx & 15;
        float4 v = make_float4(0.f, 0.f, 0.f, 0.f);
        if (row < KC) v = ((const float4*)sel_mu)[row * 16 + j4];
        const float hx = __bfloat162float(__float2bfloat16(v.x));
        const float hy = __bfloat162float(__float2bfloat16(v.y));
        const float hz = __bfloat162float(__float2bfloat16(v.z));
        const float hw = __bfloat162float(__float2bfloat16(v.w));
        uint32_t* dh = (uint32_t*)(Bh + row * APITCH + j4 * 4);
        dh[0] = pack_bf2(hx, hy); dh[1] = pack_bf2(hz, hw);
        uint32_t* dl = (uint32_t*)(Bl + row * APITCH + j4 * 4);
        dl[0] = pack_bf2(v.x - hx, v.y - hy);
        dl[1] = pack_bf2(v.z - hz, v.w - hw);
    }

    // ---- per-cluster coefficients ----
    #pragma unroll 1
    for (int k = tid; k < KPAD; k += 256) {
        float4 cf = make_float4(0.f, 0.f, 0.f, 1e30f);
        if (k < KC) {
            const float a = spa_mu[3 * k], b = spa_mu[3 * k + 1], c = spa_mu[3 * k + 2];
            float mn = a * a + b * b + c * c;
            const float4* mr = (const float4*)sel_mu + (size_t)k * 16;
            #pragma unroll
            for (int j = 0; j < 16; ++j) {
                float4 m = mr[j];
                mn += m.x * m.x + m.y * m.y + m.z * m.z + m.w * m.w;
            }
            cf = make_float4(a, b, c, 0.5f * mn);
        }
        cfp[k] = cf;
    }

    // ---- per-row constants ----
    if (tid < TILE_M) {
        const int gi = i0 + tid;
        float4 rc = make_float4(0.f, 0.f, 0.f, 0.f);
        if (gi < s) {
            float zn = 0.f;
            const float4* zr = (const float4*)Z + (size_t)gi * 16;
            #pragma unroll
            for (int j = 0; j < 16; ++j) {
                float4 z = zr[j];
                zn += z.x * z.x + z.y * z.y + z.z * z.z + z.w * z.w;
            }
            rc.x = S[(size_t)3 * gi];
            rc.y = S[(size_t)3 * gi + 1];
            rc.z = S[(size_t)3 * gi + 2];
            rc.w = zn + rc.x * rc.x + rc.y * rc.y + rc.z * rc.z;
        }
        rcp[tid] = rc;
    }
    __syncthreads();

    // ---- MMA mainloop: acc[t] += Ah*Bh + Ah*Bl + Al*Bh ----
    float acc[NTW][4];
    #pragma unroll
    for (int t = 0; t < NTW; ++t)
        acc[t][0] = acc[t][1] = acc[t][2] = acc[t][3] = 0.f;

    const int r0 = stripe * 16 + g;
    #pragma unroll
    for (int ks = 0; ks < 4; ++ks) {
        const int kb = ks * 16 + 2 * tg;
        uint32_t a_h[4], a_l[4];
        a_h[0] = *(const uint32_t*)(Ah + r0 * APITCH + kb);
        a_h[1] = *(const uint32_t*)(Ah + (r0 + 8) * APITCH + kb);
        a_h[2] = *(const uint32_t*)(Ah + r0 * APITCH + kb + 8);
        a_h[3] = *(const uint32_t*)(Ah + (r0 + 8) * APITCH + kb + 8);
        a_l[0] = *(const uint32_t*)(Al + r0 * APITCH + kb);
        a_l[1] = *(const uint32_t*)(Al + (r0 + 8) * APITCH + kb);
        a_l[2] = *(const uint32_t*)(Al + r0 * APITCH + kb + 8);
        a_l[3] = *(const uint32_t*)(Al + (r0 + 8) * APITCH + kb + 8);
        #pragma unroll
        for (int t = 0; t < NTW; ++t) {
            const int tgl = half * NTW + t;
            const __nv_bfloat16* bh = Bh + (tgl * 8 + g) * APITCH + kb;
            const __nv_bfloat16* bl = Bl + (tgl * 8 + g) * APITCH + kb;
            const uint32_t bh0 = *(const uint32_t*)bh;
            const uint32_t bh1 = *(const uint32_t*)(bh + 8);
            const uint32_t bl0 = *(const uint32_t*)bl;
            const uint32_t bl1 = *(const uint32_t*)(bl + 8);
            mma_bf16(acc[t], a_h, bh0, bh1);
            mma_bf16(acc[t], a_h, bl0, bl1);
            mma_bf16(acc[t], a_l, bh0, bh1);
        }
    }

    // ---- epilogue: logits, warp-local softmax stats ----
    const float4 rc0 = rcp[r0];
    const float4 rc1 = rcp[r0 + 8];

    float m0 = -CUDART_INF_F, m1 = -CUDART_INF_F;
    #pragma unroll
    for (int t = 0; t < NTW; ++t) {
        const int cb = (half * NTW + t) * 8 + 2 * tg;
        const float4 c0 = cfp[cb];
        const float4 c1 = cfp[cb + 1];
        acc[t][0] += rc0.x * c0.x + rc0.y * c0.y + rc0.z * c0.z - c0.w;
        acc[t][1] += rc0.x * c1.x + rc0.y * c1.y + rc0.z * c1.z - c1.w;
        acc[t][2] += rc1.x * c0.x + rc1.y * c0.y + rc1.z * c0.z - c0.w;
        acc[t][3] += rc1.x * c1.x + rc1.y * c1.y + rc1.z * c1.z - c1.w;
        m0 = fmaxf(m0, fmaxf(acc[t][0], acc[t][1]));
        m1 = fmaxf(m1, fmaxf(acc[t][2], acc[t][3]));
    }
    m0 = fmaxf(m0, __shfl_xor_sync(0xffffffffu, m0, 1));
    m0 = fmaxf(m0, __shfl_xor_sync(0xffffffffu, m0, 2));
    m1 = fmaxf(m1, __shfl_xor_sync(0xffffffffu, m1, 1));
    m1 = fmaxf(m1, __shfl_xor_sync(0xffffffffu, m1, 2));

    float se0 = 0.f, sl0 = 0.f, se1 = 0.f, sl1 = 0.f;
    #pragma unroll
    for (int t = 0; t < NTW; ++t) {
        float e;
        e = __expf(acc[t][0] - m0); se0 += e; sl0 += e * acc[t][0]; acc[t][0] = e;
        e = __expf(acc[t][1] - m0); se0 += e; sl0 += e * acc[t][1]; acc[t][1] = e;
        e = __expf(acc[t][2] - m1); se1 += e; sl1 += e * acc[t][2]; acc[t][2] = e;
        e = __expf(acc[t][3] - m1); se1 += e; sl1 += e * acc[t][3]; acc[t][3] = e;
    }
    se0 += __shfl_xor_sync(0xffffffffu, se0, 1);
    se0 += __shfl_xor_sync(0xffffffffu, se0, 2);
    sl0 += __shfl_xor_sync(0xffffffffu, sl0, 1);
    sl0 += __shfl_xor_sync(0xffffffffu, sl0, 2);
    se1 += __shfl_xor_sync(0xffffffffu, se1, 1);
    se1 += __shfl_xor_sync(0xffffffffu, se1, 2);
    sl1 += __shfl_xor_sync(0xffffffffu, sl1, 1);
    sl1 += __shfl_xor_sync(0xffffffffu, sl1, 2);

    // ---- publish warp-local stats, combine across the warp pair ----
    if (tg == 0) {
        stM [r0 * 2 + half] = m0;  stM [(r0 + 8) * 2 + half] = m1;
        stSE[r0 * 2 + half] = se0; stSE[(r0 + 8) * 2 + half] = se1;
        stSL[r0 * 2 + half] = sl0; stSL[(r0 + 8) * 2 + half] = sl1;
    }
    __syncthreads();

    float M0, M1, inv0, inv1, f0, f1;
    {
        const float ma = stM[r0 * 2], mb = stM[r0 * 2 + 1];
        M0 = fmaxf(ma, mb);
        const float wa = __expf(ma - M0), wb = __expf(mb - M0);
        const float seC = stSE[r0 * 2] * wa + stSE[r0 * 2 + 1] * wb;
        const float slC = stSL[r0 * 2] * wa + stSL[r0 * 2 + 1] * wb;
        inv0 = 1.0f / seC;
        f0 = __expf(m0 - M0) * inv0;
        const int gr0 = i0 + r0;
        if (half == 0 && tg == 0 && gr0 < s)
            out[gr0] = 0.5f * rc0.w + cpoint - slC * inv0;
    }
    {
        const int r1 = r0 + 8;
        const float ma = stM[r1 * 2], mb = stM[r1 * 2 + 1];
        M1 = fmaxf(ma, mb);
        const float wa = __expf(ma - M1), wb = __expf(mb - M1);
        const float seC = stSE[r1 * 2] * wa + stSE[r1 * 2 + 1] * wb;
        const float slC = stSL[r1 * 2] * wa + stSL[r1 * 2 + 1] * wb;
        inv1 = 1.0f / seC;
        f1 = __expf(m1 - M1) * inv1;
        const int gr1 = i0 + r1;
        if (half == 0 && tg == 0 && gr1 < s)
            out[gr1] = 0.5f * rc1.w + cpoint - slC * inv1;
    }

    // ---- store clipped Q as bf16 (point-major) ----
    const int gr0 = i0 + r0, gr1 = gr0 + 8;
    uint32_t* q0p = (uint32_t*)(g_Qc + (size_t)gr0 * KC);
    uint32_t* q1p = (uint32_t*)(g_Qc + (size_t)gr1 * KC);
    const bool v0 = (gr0 < s), v1 = (gr1 < s);
    const int tmax = NTW - half;           // half0: 13 tiles, half1: 12 (skip col>=200)
    #pragma unroll
    for (int t = 0; t < NTW; ++t) {
        if (t >= tmax) break;
        const int tgl = half * NTW + t;
        float qa = fminf(fmaxf(acc[t][0] * f0, 1e-6f), 1.0f - 1e-6f);
        float qb = fminf(fmaxf(acc[t][1] * f0, 1e-6f), 1.0f - 1e-6f);
        float qc = fminf(fmaxf(acc[t][2] * f1, 1e-6f), 1.0f - 1e-6f);
        float qd = fminf(fmaxf(acc[t][3] * f1, 1e-6f), 1.0f - 1e-6f);
        if (v0) q0p[4 * tgl + tg] = pack_bf2(qa, qb);
        if (v1) q1p[4 * tgl + tg] = pack_bf2(qc, qd);
    }
}

// ---------------- K2: doublet energy (warp/point, bf16 rows) -----------------
#define NTS 25
__global__ void __launch_bounds__(256) k2_doublet(float* __restrict__ out,
                                                  const void* __restrict__ Dv,
                                                  int s, int n)
{
    const int t = threadIdx.x, lane = t & 31, w = t >> 5;

    // dtype probe: true int64 neighbor ids are all < s; int32 data read as
    // int64 packs two ids -> almost surely >= 2^32 somewhere in 32 words.
    long long probe = ((const long long*)Dv)[lane];
    const bool ok = (probe >= 0) && (probe < (long long)s);
    const bool is64 = (__ballot_sync(0xffffffffu, ok) == 0xffffffffu);

    const int i = blockIdx.x * 8 + w;
    if (i >= s) return;

    const uint4* Q4 = (const uint4*)g_Qc;   // row = 25 uint4 (200 bf16)
    const uint4 zero4 = make_uint4(0, 0, 0, 0);
    const uint4 ov = (lane < NTS) ? Q4[(size_t)i * NTS + lane] : zero4;
    float of[8];
    {
        const uint32_t* p = (const uint32_t*)&ov;
        #pragma unroll
        for (int j = 0; j < 4; ++j) {
            float2 f = __bfloat1622float2(*(const __nv_bfloat162*)&p[j]);
            of[2 * j] = f.x; of[2 * j + 1] = f.y;
        }
    }

    float doublet = 0.f;
    for (int base = 0; base < n; base += 6) {
        float acc[6]; int val[6];
        #pragma unroll
        for (int nb = 0; nb < 6; ++nb) {
            acc[nb] = 1.f; val[nb] = 0;
            const int q = base + nb;
            if (q < n) {
                long long d = is64 ? ((const long long*)Dv)[(size_t)i * n + q]
                                   : (long long)((const int*)Dv)[(size_t)i * n + q];
                val[nb] = (d >= 0 && d < s) ? 1 : 0;
                const size_t ridx = (size_t)(val[nb] ? (int)d : i) * NTS;
                const uint4 nv = (lane < NTS) ? Q4[ridx + lane] : zero4;
                const uint32_t* p = (const uint32_t*)&nv;
                float a = 0.f;
                #pragma unroll
                for (int j = 0; j < 4; ++j) {
                    float2 f = __bfloat1622float2(*(const __nv_bfloat162*)&p[j]);
                    a += of[2 * j] * f.x + of[2 * j + 1] * f.y;
                }
                acc[nb] = a;
            }
        }
        #pragma unroll
        for (int off = 16; off; off >>= 1) {
            #pragma unroll
            for (int nb = 0; nb < 6; ++nb)
                acc[nb] += __shfl_xor_sync(0xffffffffu, acc[nb], off);
        }
        #pragma unroll
        for (int nb = 0; nb < 6; ++nb)
            if (val[nb]) doublet -= __logf(acc[nb]);
    }
    if (lane == 0) out[i] += doublet;
}

// ---------------- launch -----------------------------------------------------
extern "C" void kernel_launch(void* const* d_in, const int* in_sizes, int n_in,
                              void* d_out, int out_size)
{
    const float* Z      = (const float*)d_in[0];
    const float* S      = (const float*)d_in[1];
    const void*  D      = d_in[2];
    const float* sel_mu = (const float*)d_in[3];
    const float* spa_mu = (const float*)d_in[4];
    float* out = (float*)d_out;

    const int s  = in_sizes[1] / 3;
    const int dz = in_sizes[0] / s;
    const int n  = in_sizes[2] / s;
    const float cpoint = 0.5f * (float)(dz + 3) * 1.8378770664093453f;

    static bool attr_set = false;
    if (!attr_set) {
        cudaFuncSetAttribute(k1_fused,
                             cudaFuncAttributeMaxDynamicSharedMemorySize,
                             SMEM_SZ);
        attr_set = true;
    }

    k1_fused<<<(s + TILE_M - 1) / TILE_M, 256, SMEM_SZ>>>(
        Z, S, sel_mu, spa_mu, out, s, cpoint);
    k2_doublet<<<(s + 7) / 8, 256>>>(out, D, s, n);
}